// round 2
// baseline (speedup 1.0000x reference)
#include <cuda_runtime.h>
#include <cuda_bf16.h>

#define BB 16
#define DD 512
#define TT 4096
#define KK 1024

#define TILE_T 128
#define TILE_K 128
#define TILE_D 32

__device__ float g_csq[KK];

// ---------------------------------------------------------------------------
// c_sq[k] = sum_d codebook[k][d]^2   (one warp per row)
// ---------------------------------------------------------------------------
__global__ void csq_kernel(const float* __restrict__ cb) {
    int warp = (blockIdx.x * blockDim.x + threadIdx.x) >> 5;
    int lane = threadIdx.x & 31;
    if (warp < KK) {
        const float* row = cb + (size_t)warp * DD;
        float s = 0.f;
        #pragma unroll
        for (int d = lane; d < DD; d += 32) { float v = row[d]; s += v * v; }
        #pragma unroll
        for (int o = 16; o; o >>= 1) s += __shfl_xor_sync(0xFFFFFFFFu, s, o);
        if (lane == 0) g_csq[warp] = s;
    }
}

// ---------------------------------------------------------------------------
// Fused distance-GEMM + argmin + gather.
// Block: 128 t-points of one batch. Threads: 16(t) x 16(k), 8x8 accumulators.
// dist surrogate: s[k] = c_sq[k] - 2 * <x_t, c_k>   (x_sq drops from argmin)
// ---------------------------------------------------------------------------
__global__ __launch_bounds__(256, 2)
void vq_kernel(const float* __restrict__ x, const float* __restrict__ cb,
               float* __restrict__ qout, float* __restrict__ iout) {
    __shared__ float xs[TILE_D][TILE_T];       // 16 KB
    __shared__ float cs[TILE_K][TILE_D + 1];   // ~16.5 KB (pad kills conflicts)
    __shared__ float redv[16][TILE_T];         // 8 KB
    __shared__ int   redi[16][TILE_T];         // 8 KB
    __shared__ float bestv[TILE_T];
    __shared__ int   besti[TILE_T];

    const int tid = threadIdx.x;
    const int tx  = tid & 15;    // t group: t_local = tx*8 + i
    const int ty  = tid >> 4;    // k group: k_local = ty*8 + j
    const int blk = blockIdx.x;
    const int b   = blk / (TT / TILE_T);
    const int t0  = (blk % (TT / TILE_T)) * TILE_T;

    const float* xb = x + (size_t)b * DD * TT + t0;   // x[b, d, t0 + ...]

    if (tid < TILE_T) { bestv[tid] = 3.4e38f; besti[tid] = 0; }

    for (int k0 = 0; k0 < KK; k0 += TILE_K) {
        float acc[8][8];
        #pragma unroll
        for (int i = 0; i < 8; i++)
            #pragma unroll
            for (int j = 0; j < 8; j++) acc[i][j] = 0.f;

        for (int d0 = 0; d0 < DD; d0 += TILE_D) {
            __syncthreads();
            // load x tile: TILE_D x TILE_T = 1024 float4, 4 per thread, coalesced
            #pragma unroll
            for (int l = 0; l < 4; l++) {
                int e   = l * 256 + tid;
                int row = e >> 5;          // /(TILE_T/4)
                int col = e & 31;
                float4 v = *(const float4*)(xb + (size_t)(d0 + row) * TT + col * 4);
                *(float4*)&xs[row][col * 4] = v;
            }
            // load codebook tile: TILE_K x TILE_D = 1024 float4, coalesced rows
            #pragma unroll
            for (int l = 0; l < 4; l++) {
                int e   = l * 256 + tid;
                int row = e >> 3;          // /(TILE_D/4)
                int col = e & 7;
                float4 v = *(const float4*)(cb + (size_t)(k0 + row) * DD + d0 + col * 4);
                cs[row][col * 4 + 0] = v.x; cs[row][col * 4 + 1] = v.y;
                cs[row][col * 4 + 2] = v.z; cs[row][col * 4 + 3] = v.w;
            }
            __syncthreads();

            #pragma unroll
            for (int d = 0; d < TILE_D; d++) {
                float xv[8], cv[8];
                float4 a0 = *(const float4*)&xs[d][tx * 8];
                float4 a1 = *(const float4*)&xs[d][tx * 8 + 4];
                xv[0]=a0.x; xv[1]=a0.y; xv[2]=a0.z; xv[3]=a0.w;
                xv[4]=a1.x; xv[5]=a1.y; xv[6]=a1.z; xv[7]=a1.w;
                #pragma unroll
                for (int j = 0; j < 8; j++) cv[j] = cs[ty * 8 + j][d];
                #pragma unroll
                for (int i = 0; i < 8; i++)
                    #pragma unroll
                    for (int j = 0; j < 8; j++)
                        acc[i][j] = fmaf(xv[i], cv[j], acc[i][j]);
            }
        }

        // per-thread argmin over its 8 k values for each of its 8 t values
        #pragma unroll
        for (int i = 0; i < 8; i++) {
            float mv = 3.4e38f; int mi = 0;
            #pragma unroll
            for (int j = 0; j < 8; j++) {
                int k = k0 + ty * 8 + j;             // ascending within thread
                float s = g_csq[k] - 2.f * acc[i][j];
                if (s < mv) { mv = s; mi = k; }      // strict < keeps lowest idx
            }
            redv[ty][tx * 8 + i] = mv;
            redi[ty][tx * 8 + i] = mi;
        }
        __syncthreads();
        if (tid < TILE_T) {
            float mv = bestv[tid]; int mi = besti[tid];
            #pragma unroll
            for (int r = 0; r < 16; r++) {           // ascending k groups
                float v = redv[r][tid]; int ii = redi[r][tid];
                if (v < mv || (v == mv && ii < mi)) { mv = v; mi = ii; }
            }
            bestv[tid] = mv; besti[tid] = mi;
        }
        __syncthreads();
    }

    // write indexes (as float: numeric compare vs jnp int argmin)
    if (tid < TILE_T) iout[(size_t)b * TT + t0 + tid] = (float)besti[tid];
    __syncthreads();

    // gather quantized: qout[b, d, t0+t] = cb[besti[t], d]; stores coalesced in t
    float* qb = qout + (size_t)b * DD * TT + t0;
    for (int e = tid; e < DD * TILE_T; e += 256) {
        int t = e & (TILE_T - 1);
        int d = e >> 7;
        qb[(size_t)d * TT + t] = cb[(size_t)besti[t] * DD + d];
    }
}

extern "C" void kernel_launch(void* const* d_in, const int* in_sizes, int n_in,
                              void* d_out, int out_size) {
    const float* x  = (const float*)d_in[0];   // [B, D, T] fp32
    const float* cb = (const float*)d_in[1];   // [K, D]    fp32

    float* qout = (float*)d_out;                         // [B, D, T]
    float* iout = (float*)d_out + (size_t)BB * DD * TT;  // [B, T] as float

    csq_kernel<<<(KK * 32 + 255) / 256, 256>>>(cb);
    vq_kernel<<<(BB * TT) / TILE_T, 256>>>(x, cb, qout, iout);
}

// round 4
// speedup vs baseline: 1.0441x; 1.0441x over previous
#include <cuda_runtime.h>
#include <cuda_bf16.h>
#include <cstdint>

#define BB 16
#define DD 512
#define TT 4096
#define KK 1024

#define TILE_T 128
#define TILE_K 128
#define TILE_D 32
#define CS_STRIDE (TILE_K + 4)   // 132 floats: 16B-aligned rows, staggered banks

__device__ float g_csq[KK];

// ---------------- packed f32x2 helpers (base PTX, sm_100+) ----------------
__device__ __forceinline__ void fma2(unsigned long long& acc,
                                     unsigned long long a, unsigned long long b) {
    asm("fma.rn.f32x2 %0, %1, %2, %0;" : "+l"(acc) : "l"(a), "l"(b));
}
__device__ __forceinline__ unsigned long long bcast2(float x) {
    unsigned long long r;
    asm("mov.b64 %0, {%1, %1};" : "=l"(r) : "r"(__float_as_uint(x)));
    return r;
}
__device__ __forceinline__ float2 unpk(unsigned long long v) {
    unsigned lo, hi;
    asm("mov.b64 {%0, %1}, %2;" : "=r"(lo), "=r"(hi) : "l"(v));
    return make_float2(__uint_as_float(lo), __uint_as_float(hi));
}

// ---------------------------------------------------------------------------
// c_sq[k] = sum_d codebook[k][d]^2   (one warp per row)
// ---------------------------------------------------------------------------
__global__ void csq_kernel(const float* __restrict__ cb) {
    int warp = (blockIdx.x * blockDim.x + threadIdx.x) >> 5;
    int lane = threadIdx.x & 31;
    if (warp < KK) {
        const float* row = cb + (size_t)warp * DD;
        float s = 0.f;
        #pragma unroll
        for (int d = lane; d < DD; d += 32) { float v = row[d]; s += v * v; }
        #pragma unroll
        for (int o = 16; o; o >>= 1) s += __shfl_xor_sync(0xFFFFFFFFu, s, o);
        if (lane == 0) g_csq[warp] = s;
    }
}

// ---------------------------------------------------------------------------
// Fused distance-GEMM (packed f32x2 FMA) + argmin + gather.
// Block: 128 t-points of one batch. Threads 16(t) x 16(k).
// Each thread: 8 t-values x 4 k-pairs (=8 k) of f32x2 accumulators.
// dist surrogate s[k] = c_sq[k] - 2 * <x_t, c_k>  (x_sq drops from argmin)
// ---------------------------------------------------------------------------
__global__ __launch_bounds__(256, 2)
void vq_kernel(const float* __restrict__ x, const float* __restrict__ cb,
               float* __restrict__ qout, float* __restrict__ iout) {
    __shared__ __align__(16) float xs[TILE_D][TILE_T];      // 16 KB
    __shared__ __align__(16) float cs_t[TILE_D][CS_STRIDE]; // 16.5 KB (transposed)
    __shared__ float redv[16][TILE_T];                      // 8 KB
    __shared__ int   redi[16][TILE_T];                      // 8 KB
    __shared__ float bestv[TILE_T];
    __shared__ int   besti[TILE_T];

    const int tid = threadIdx.x;
    const int tx  = tid & 15;    // t group: t_local = tx*8 + i
    const int ty  = tid >> 4;    // k group: k_local = ty*8 + 2*j (+lane)
    const int blk = blockIdx.x;
    const int b   = blk / (TT / TILE_T);
    const int t0  = (blk % (TT / TILE_T)) * TILE_T;

    const float* xb = x + (size_t)b * DD * TT + t0;   // x[b, d, t0 + ...]

    if (tid < TILE_T) { bestv[tid] = 3.4e38f; besti[tid] = 0; }

    for (int k0 = 0; k0 < KK; k0 += TILE_K) {
        unsigned long long acc2[8][4];
        #pragma unroll
        for (int i = 0; i < 8; i++)
            #pragma unroll
            for (int j = 0; j < 4; j++) acc2[i][j] = 0ull;

        for (int d0 = 0; d0 < DD; d0 += TILE_D) {
            __syncthreads();
            // x tile: TILE_D x TILE_T = 1024 float4, 4/thread, coalesced
            #pragma unroll
            for (int l = 0; l < 4; l++) {
                int e   = l * 256 + tid;
                int row = e >> 5;
                int col = e & 31;
                float4 v = *(const float4*)(xb + (size_t)(d0 + row) * TT + col * 4);
                *(float4*)&xs[row][col * 4] = v;
            }
            // codebook tile, TRANSPOSED into cs_t[d][k]: coalesced gmem reads
            #pragma unroll
            for (int l = 0; l < 4; l++) {
                int e   = l * 256 + tid;
                int k   = e >> 3;          // 0..127
                int j   = e & 7;           // d-quad 0..7
                float4 v = *(const float4*)(cb + (size_t)(k0 + k) * DD + d0 + 4 * j);
                cs_t[4 * j + 0][k] = v.x;
                cs_t[4 * j + 1][k] = v.y;
                cs_t[4 * j + 2][k] = v.z;
                cs_t[4 * j + 3][k] = v.w;
            }
            __syncthreads();

            #pragma unroll
            for (int d = 0; d < TILE_D; d++) {
                // 8 consecutive k-values for this thread = 4 packed pairs
                ulonglong2 c01 = *(const ulonglong2*)&cs_t[d][ty * 8];
                ulonglong2 c23 = *(const ulonglong2*)&cs_t[d][ty * 8 + 4];
                unsigned long long cvp[4] = {c01.x, c01.y, c23.x, c23.y};

                float4 a0 = *(const float4*)&xs[d][tx * 8];
                float4 a1 = *(const float4*)&xs[d][tx * 8 + 4];
                unsigned long long xv2[8];
                xv2[0] = bcast2(a0.x); xv2[1] = bcast2(a0.y);
                xv2[2] = bcast2(a0.z); xv2[3] = bcast2(a0.w);
                xv2[4] = bcast2(a1.x); xv2[5] = bcast2(a1.y);
                xv2[6] = bcast2(a1.z); xv2[7] = bcast2(a1.w);

                #pragma unroll
                for (int i = 0; i < 8; i++)
                    #pragma unroll
                    for (int j = 0; j < 4; j++)
                        fma2(acc2[i][j], xv2[i], cvp[j]);
            }
        }

        // per-thread argmin over its 8 k values for each of its 8 t values
        #pragma unroll
        for (int i = 0; i < 8; i++) {
            float mv = 3.4e38f; int mi = 0;
            #pragma unroll
            for (int j = 0; j < 4; j++) {            // ascending k pairs
                const int k = k0 + ty * 8 + 2 * j;
                float2 cr = unpk(acc2[i][j]);
                float s0 = g_csq[k]     - 2.f * cr.x;
                float s1 = g_csq[k + 1] - 2.f * cr.y;
                if (s0 < mv) { mv = s0; mi = k; }     // strict <: lowest k wins
                if (s1 < mv) { mv = s1; mi = k + 1; }
            }
            redv[ty][tx * 8 + i] = mv;
            redi[ty][tx * 8 + i] = mi;
        }
        __syncthreads();
        if (tid < TILE_T) {
            float mv = bestv[tid]; int mi = besti[tid];
            #pragma unroll
            for (int r = 0; r < 16; r++) {           // ascending k groups
                float v = redv[r][tid]; int ii = redi[r][tid];
                if (v < mv || (v == mv && ii < mi)) { mv = v; mi = ii; }
            }
            bestv[tid] = mv; besti[tid] = mi;
        }
        __syncthreads();
    }

    // indexes (as float: numeric compare vs jnp int argmin)
    if (tid < TILE_T) iout[(size_t)b * TT + t0 + tid] = (float)besti[tid];
    __syncthreads();

    // gather quantized: qout[b, d, t0+t] = cb[besti[t], d]; t-coalesced stores
    float* qb = qout + (size_t)b * DD * TT + t0;
    for (int e = tid; e < DD * TILE_T; e += 256) {
        int t = e & (TILE_T - 1);
        int d = e >> 7;
        qb[(size_t)d * TT + t] = cb[(size_t)besti[t] * DD + d];
    }
}

extern "C" void kernel_launch(void* const* d_in, const int* in_sizes, int n_in,
                              void* d_out, int out_size) {
    const float* x  = (const float*)d_in[0];   // [B, D, T] fp32
    const float* cb = (const float*)d_in[1];   // [K, D]    fp32

    float* qout = (float*)d_out;                         // [B, D, T]
    float* iout = (float*)d_out + (size_t)BB * DD * TT;  // [B, T] as float

    csq_kernel<<<(KK * 32 + 255) / 256, 256>>>(cb);
    vq_kernel<<<(BB * TT) / TILE_T, 256>>>(x, cb, qout, iout);
}

// round 6
// speedup vs baseline: 1.1211x; 1.0737x over previous
#include <cuda_runtime.h>
#include <cuda_bf16.h>
#include <cstdint>

#define BB 16
#define DD 512
#define TT 4096
#define KK 1024

#define TILE_T 128
#define TILE_K 128
#define TILE_D 32
#define N_CHUNKS ((KK / TILE_K) * (DD / TILE_D))   // 8 * 16 = 128
#define CS_ROW 36                                   // 32 + 4 pad floats

// ---- dynamic smem layout (float offsets) ----
#define F_XS    0                      // 2 stages x 32*128      = 8192 floats
#define F_CS    8192                   // 2 stages x 128*36      = 9216 floats
#define F_REDV  17408                  // 16*128                 = 2048
#define F_REDI  19456                  // 16*128                 = 2048
#define F_BESTV 21504                  // 128
#define F_BESTI 21632                  // 128
#define SMEM_FLOATS 21760
#define SMEM_BYTES  (SMEM_FLOATS * 4)  // 87040 B -> occ 2 by smem

__device__ float g_csq[KK];

// ---------------- helpers ----------------
__device__ __forceinline__ void fma2(unsigned long long& acc,
                                     unsigned long long a, unsigned long long b) {
    asm("fma.rn.f32x2 %0, %1, %2, %0;" : "+l"(acc) : "l"(a), "l"(b));
}
__device__ __forceinline__ unsigned long long bcast2(float x) {
    unsigned long long r;
    asm("mov.b64 %0, {%1, %1};" : "=l"(r) : "r"(__float_as_uint(x)));
    return r;
}
__device__ __forceinline__ float2 unpk(unsigned long long v) {
    unsigned lo, hi;
    asm("mov.b64 {%0, %1}, %2;" : "=r"(lo), "=r"(hi) : "l"(v));
    return make_float2(__uint_as_float(lo), __uint_as_float(hi));
}
__device__ __forceinline__ uint32_t smem_u32(const void* p) {
    uint32_t a;
    asm("{ .reg .u64 t; cvta.to.shared.u64 t, %1; cvt.u32.u64 %0, t; }" : "=r"(a) : "l"(p));
    return a;
}
__device__ __forceinline__ void cp16(uint32_t dst, const void* src) {
    asm volatile("cp.async.cg.shared.global [%0], [%1], 16;" :: "r"(dst), "l"(src));
}
#define CP_COMMIT() asm volatile("cp.async.commit_group;" ::: "memory")
#define CP_WAIT1()  asm volatile("cp.async.wait_group 1;" ::: "memory")
#define CP_WAIT0()  asm volatile("cp.async.wait_group 0;" ::: "memory")

// ---------------------------------------------------------------------------
__global__ void csq_kernel(const float* __restrict__ cb) {
    int warp = (blockIdx.x * blockDim.x + threadIdx.x) >> 5;
    int lane = threadIdx.x & 31;
    if (warp < KK) {
        const float* row = cb + (size_t)warp * DD;
        float s = 0.f;
        #pragma unroll
        for (int d = lane; d < DD; d += 32) { float v = row[d]; s += v * v; }
        #pragma unroll
        for (int o = 16; o; o >>= 1) s += __shfl_xor_sync(0xFFFFFFFFu, s, o);
        if (lane == 0) g_csq[warp] = s;
    }
}

// ---------------------------------------------------------------------------
// cp.async double-buffered fused distance-GEMM (f32x2) + argmin + gather.
// 256 threads = 16(tx: t) x 16(ty: k). Per thread: 4 t-pairs x 8 k.
// ---------------------------------------------------------------------------
__global__ __launch_bounds__(256, 2)
void vq_kernel(const float* __restrict__ x, const float* __restrict__ cb,
               float* __restrict__ qout, float* __restrict__ iout) {
    extern __shared__ float sm[];
    float* XS    = sm + F_XS;
    float* CS    = sm + F_CS;
    float* redv  = sm + F_REDV;
    int*   redi  = (int*)(sm + F_REDI);
    float* bestv = sm + F_BESTV;
    int*   besti = (int*)(sm + F_BESTI);

    const int tid = threadIdx.x;
    const int tx  = tid & 15;     // t group: t = tx*8 + (0..7)
    const int ty  = tid >> 4;     // k group: k = ty*8 + (0..7)
    const int blk = blockIdx.x;
    const int b   = blk >> 5;     // 32 t-tiles per batch
    const int t0  = (blk & 31) << 7;

    const float* xb = x + (size_t)b * DD * TT + t0;

    const uint32_t xs_u = smem_u32(XS);
    const uint32_t cs_u = smem_u32(CS);

    if (tid < TILE_T) { bestv[tid] = 3.4e38f; besti[tid] = 0; }

    // ---- issue chunk c's tiles into stage s ----
    auto issue = [&](int c, int s) {
        const int k0 = (c >> 4) << 7;
        const int d0 = (c & 15) << 5;
        const uint32_t xdst = xs_u + (uint32_t)(s * 4096 * 4);
        const uint32_t cdst = cs_u + (uint32_t)(s * 4608 * 4);
        #pragma unroll
        for (int l = 0; l < 4; l++) {            // x: 32d x 128t, 1024 x 16B
            int e  = l * 256 + tid;
            int d  = e >> 5;
            int t4 = e & 31;
            cp16(xdst + (uint32_t)((d * 128 + t4 * 4) * 4),
                 xb + (size_t)(d0 + d) * TT + t4 * 4);
        }
        #pragma unroll
        for (int l = 0; l < 4; l++) {            // cb: 128k x 32d, 1024 x 16B
            int e  = l * 256 + tid;
            int k  = e >> 3;
            int dq = e & 7;
            cp16(cdst + (uint32_t)((k * CS_ROW + dq * 4) * 4),
                 cb + (size_t)(k0 + k) * DD + d0 + dq * 4);
        }
        CP_COMMIT();
    };

    unsigned long long acc2[4][8];
    #pragma unroll
    for (int p = 0; p < 4; p++)
        #pragma unroll
        for (int j = 0; j < 8; j++) acc2[p][j] = 0ull;

    issue(0, 0);

    for (int c = 0; c < N_CHUNKS; c++) {
        const int s = c & 1;
        if (c + 1 < N_CHUNKS) issue(c + 1, s ^ 1);
        if (c + 1 < N_CHUNKS) { CP_WAIT1(); } else { CP_WAIT0(); }
        __syncthreads();

        const float* xsS = XS + s * 4096;
        const float* csS = CS + s * 4608 + ty * 8 * CS_ROW;

        // ---- compute: 32 d-steps, d-pairs for cs vector loads ----
        #pragma unroll
        for (int d2 = 0; d2 < 16; d2++) {
            float2 cf[8];
            #pragma unroll
            for (int j = 0; j < 8; j++)
                cf[j] = *(const float2*)(csS + j * CS_ROW + d2 * 2);
            #pragma unroll
            for (int dd = 0; dd < 2; dd++) {
                const int d = d2 * 2 + dd;
                ulonglong2 xa = *(const ulonglong2*)(xsS + d * 128 + tx * 8);
                ulonglong2 xc = *(const ulonglong2*)(xsS + d * 128 + tx * 8 + 4);
                unsigned long long xp0 = xa.x, xp1 = xa.y, xp2 = xc.x, xp3 = xc.y;
                #pragma unroll
                for (int j = 0; j < 8; j++) {
                    unsigned long long cc = bcast2(dd == 0 ? cf[j].x : cf[j].y);
                    fma2(acc2[0][j], xp0, cc);
                    fma2(acc2[1][j], xp1, cc);
                    fma2(acc2[2][j], xp2, cc);
                    fma2(acc2[3][j], xp3, cc);
                }
            }
        }

        // ---- end of a k-pass: fold argmin, reset acc ----
        if ((c & 15) == 15) {
            const int k0 = (c >> 4) << 7;
            #pragma unroll
            for (int p = 0; p < 4; p++) {
                float mv0 = 3.4e38f, mv1 = 3.4e38f;
                int   mi0 = 0,       mi1 = 0;
                #pragma unroll
                for (int j = 0; j < 8; j++) {          // ascending k
                    const int k = k0 + ty * 8 + j;
                    const float cq = __ldg(&g_csq[k]);
                    float2 cr = unpk(acc2[p][j]);
                    float s0 = cq - 2.f * cr.x;
                    float s1 = cq - 2.f * cr.y;
                    if (s0 < mv0) { mv0 = s0; mi0 = k; }
                    if (s1 < mv1) { mv1 = s1; mi1 = k; }
                    acc2[p][j] = 0ull;
                }
                redv[ty * 128 + tx * 8 + 2 * p]     = mv0;
                redi[ty * 128 + tx * 8 + 2 * p]     = mi0;
                redv[ty * 128 + tx * 8 + 2 * p + 1] = mv1;
                redi[ty * 128 + tx * 8 + 2 * p + 1] = mi1;
            }
            __syncthreads();
            if (tid < TILE_T) {
                float mv = bestv[tid]; int mi = besti[tid];
                #pragma unroll
                for (int r = 0; r < 16; r++) {         // ascending k groups
                    float v = redv[r * 128 + tid]; int ii = redi[r * 128 + tid];
                    if (v < mv || (v == mv && ii < mi)) { mv = v; mi = ii; }
                }
                bestv[tid] = mv; besti[tid] = mi;
            }
        }
        __syncthreads();   // stage s safe to overwrite next iteration
    }

    // ---- outputs ----
    if (tid < TILE_T) iout[(size_t)b * TT + t0 + tid] = (float)besti[tid];
    __syncthreads();

    float* qb = qout + (size_t)b * DD * TT + t0;
    for (int e = tid; e < DD * TILE_T; e += 256) {
        int t = e & (TILE_T - 1);
        int d = e >> 7;
        qb[(size_t)d * TT + t] = cb[(size_t)besti[t] * DD + d];
    }
}

extern "C" void kernel_launch(void* const* d_in, const int* in_sizes, int n_in,
                              void* d_out, int out_size) {
    const float* x  = (const float*)d_in[0];   // [B, D, T] fp32
    const float* cb = (const float*)d_in[1];   // [K, D]    fp32

    float* qout = (float*)d_out;                         // [B, D, T]
    float* iout = (float*)d_out + (size_t)BB * DD * TT;  // [B, T] as float

    cudaFuncSetAttribute(vq_kernel, cudaFuncAttributeMaxDynamicSharedMemorySize,
                         SMEM_BYTES);

    csq_kernel<<<(KK * 32 + 255) / 256, 256>>>(cb);
    vq_kernel<<<(BB * TT) / TILE_T, 256, SMEM_BYTES>>>(x, cb, qout, iout);
}

// round 7
// speedup vs baseline: 1.3547x; 1.2084x over previous
#include <cuda_runtime.h>
#include <cuda_bf16.h>
#include <cstdint>

#define BB 16
#define DD 512
#define TT 4096
#define KK 1024

#define TILE_T 128
#define TILE_K 128
#define TILE_D 32
#define N_CHUNKS ((KK / TILE_K) * (DD / TILE_D))   // 128
#define XS_STRIDE 136                  // 128 t + 8 pad (A-frag conflict-free)
#define XS_FL (TILE_D * XS_STRIDE)     // 4352 floats per stage
#define CS_ROW 36                      // 32 d + 4 pad (B-frag conflict-free)
#define CS_FL (TILE_K * CS_ROW)        // 4608 floats per stage

// ---- dynamic smem layout (float offsets) ----
#define F_XS    0                      // 2 x 4352 = 8704
#define F_CS    8704                   // 2 x 4608 = 9216
#define F_REDV  17920                  // 2048
#define F_REDI  19968                  // 2048
#define F_BESTV 22016                  // 128
#define F_BESTI 22144                  // 128
#define SMEM_FLOATS 22272
#define SMEM_BYTES  (SMEM_FLOATS * 4)  // 89088 B -> occ 2

__device__ float g_csq[KK];

// ---------------- helpers ----------------
__device__ __forceinline__ uint32_t smem_u32(const void* p) {
    uint32_t a;
    asm("{ .reg .u64 t; cvta.to.shared.u64 t, %1; cvt.u32.u64 %0, t; }" : "=r"(a) : "l"(p));
    return a;
}
__device__ __forceinline__ void cp16(uint32_t dst, const void* src) {
    asm volatile("cp.async.cg.shared.global [%0], [%1], 16;" :: "r"(dst), "l"(src));
}
#define CP_COMMIT() asm volatile("cp.async.commit_group;" ::: "memory")
#define CP_WAIT1()  asm volatile("cp.async.wait_group 1;" ::: "memory")
#define CP_WAIT0()  asm volatile("cp.async.wait_group 0;" ::: "memory")

// tf32 hi/lo split (Markidis): v ~= hi + lo, both tf32-valued
__device__ __forceinline__ void split_tf32(float v, uint32_t& h, uint32_t& l) {
    uint32_t hb;
    asm("cvt.rna.tf32.f32 %0, %1;" : "=r"(hb) : "f"(v));
    float hf = __uint_as_float(hb);
    asm("cvt.rna.tf32.f32 %0, %1;" : "=r"(l) : "f"(v - hf));
    h = hb;
}

// D(16x8,f32) += A(16x8 tf32, row) * B(8x8 tf32, col)
__device__ __forceinline__ void mma_tf32(float* d, const uint32_t* a, const uint32_t* b) {
    asm volatile(
        "mma.sync.aligned.m16n8k8.row.col.f32.tf32.tf32.f32 "
        "{%0,%1,%2,%3}, {%4,%5,%6,%7}, {%8,%9}, {%0,%1,%2,%3};"
        : "+f"(d[0]), "+f"(d[1]), "+f"(d[2]), "+f"(d[3])
        : "r"(a[0]), "r"(a[1]), "r"(a[2]), "r"(a[3]), "r"(b[0]), "r"(b[1]));
}

// ---------------------------------------------------------------------------
__global__ void csq_kernel(const float* __restrict__ cb) {
    int warp = (blockIdx.x * blockDim.x + threadIdx.x) >> 5;
    int lane = threadIdx.x & 31;
    if (warp < KK) {
        const float* row = cb + (size_t)warp * DD;
        float s = 0.f;
        #pragma unroll
        for (int d = lane; d < DD; d += 32) { float v = row[d]; s += v * v; }
        #pragma unroll
        for (int o = 16; o; o >>= 1) s += __shfl_xor_sync(0xFFFFFFFFu, s, o);
        if (lane == 0) g_csq[warp] = s;
    }
}

// ---------------------------------------------------------------------------
// HMMA tf32x3 fused distance-GEMM + argmin + gather.
// 256 threads = 8 warps: warp grid 2(m: t) x 4(n: k). Warp tile 64t x 32k.
// ---------------------------------------------------------------------------
__global__ __launch_bounds__(256, 2)
void vq_kernel(const float* __restrict__ x, const float* __restrict__ cb,
               float* __restrict__ qout, float* __restrict__ iout) {
    extern __shared__ float sm[];
    float* XS    = sm + F_XS;
    float* CS    = sm + F_CS;
    float* redv  = sm + F_REDV;
    int*   redi  = (int*)(sm + F_REDI);
    float* bestv = sm + F_BESTV;
    int*   besti = (int*)(sm + F_BESTI);

    const int tid    = threadIdx.x;
    const int wid    = tid >> 5;
    const int lane   = tid & 31;
    const int gid    = lane >> 2;       // 0..7
    const int tig    = lane & 3;        // 0..3
    const int warp_m = wid >> 2;        // 0..1 -> t base
    const int warp_n = wid & 3;         // 0..3 -> k base
    const int tbase  = warp_m * 64;
    const int wbase  = warp_n * 32;

    const int blk = blockIdx.x;
    const int b   = blk >> 5;
    const int t0  = (blk & 31) << 7;

    const float* xb = x + (size_t)b * DD * TT + t0;

    const uint32_t xs_u = smem_u32(XS);
    const uint32_t cs_u = smem_u32(CS);

    if (tid < TILE_T) { bestv[tid] = 3.4e38f; besti[tid] = 0; }

    // ---- issue chunk c's tiles into stage s (cp.async) ----
    auto issue = [&](int c, int s) {
        const int k0 = (c >> 4) << 7;
        const int d0 = (c & 15) << 5;
        const uint32_t xdst = xs_u + (uint32_t)(s * XS_FL * 4);
        const uint32_t cdst = cs_u + (uint32_t)(s * CS_FL * 4);
        #pragma unroll
        for (int l = 0; l < 4; l++) {            // x: 32d x 128t
            int e  = l * 256 + tid;
            int d  = e >> 5;
            int t4 = e & 31;
            cp16(xdst + (uint32_t)((d * XS_STRIDE + t4 * 4) * 4),
                 xb + (size_t)(d0 + d) * TT + t4 * 4);
        }
        #pragma unroll
        for (int l = 0; l < 4; l++) {            // cb: 128k x 32d
            int e  = l * 256 + tid;
            int k  = e >> 3;
            int dq = e & 7;
            cp16(cdst + (uint32_t)((k * CS_ROW + dq * 4) * 4),
                 cb + (size_t)(k0 + k) * DD + d0 + dq * 4);
        }
        CP_COMMIT();
    };

    // accumulators: 4 m-tiles x 4 n-tiles x 4 f32
    float acc[4][4][4];
    #pragma unroll
    for (int m = 0; m < 4; m++)
        #pragma unroll
        for (int n = 0; n < 4; n++)
            #pragma unroll
            for (int r = 0; r < 4; r++) acc[m][n][r] = 0.f;

    issue(0, 0);

    for (int c = 0; c < N_CHUNKS; c++) {
        const int s = c & 1;
        if (c + 1 < N_CHUNKS) issue(c + 1, s ^ 1);
        if (c + 1 < N_CHUNKS) { CP_WAIT1(); } else { CP_WAIT0(); }
        __syncthreads();

        const float* xsS = XS + s * XS_FL;
        const float* csS = CS + s * CS_FL;

        #pragma unroll
        for (int ds = 0; ds < 4; ds++) {
            const int dA = ds * 8 + tig;
            // A fragments (x): a0:(gid,tig) a1:(gid+8,tig) a2:(gid,tig+4) a3:(gid+8,tig+4)
            uint32_t ah[4][4], al[4][4];
            #pragma unroll
            for (int m = 0; m < 4; m++) {
                const int t = tbase + m * 16 + gid;
                split_tf32(xsS[dA * XS_STRIDE + t],           ah[m][0], al[m][0]);
                split_tf32(xsS[dA * XS_STRIDE + t + 8],       ah[m][1], al[m][1]);
                split_tf32(xsS[(dA + 4) * XS_STRIDE + t],     ah[m][2], al[m][2]);
                split_tf32(xsS[(dA + 4) * XS_STRIDE + t + 8], ah[m][3], al[m][3]);
            }
            #pragma unroll
            for (int n = 0; n < 4; n++) {
                // B fragments (cb): b0:(row=tig, col=gid) b1:(row=tig+4, col=gid)
                const int kr = wbase + n * 8 + gid;
                uint32_t bh[2], bl[2];
                split_tf32(csS[kr * CS_ROW + ds * 8 + tig],     bh[0], bl[0]);
                split_tf32(csS[kr * CS_ROW + ds * 8 + tig + 4], bh[1], bl[1]);
                #pragma unroll
                for (int m = 0; m < 4; m++) {
                    mma_tf32(acc[m][n], ah[m], bh);   // hi*hi
                    mma_tf32(acc[m][n], ah[m], bl);   // hi*lo
                    mma_tf32(acc[m][n], al[m], bh);   // lo*hi
                }
            }
        }

        // ---- end of a k-pass: fold argmin, reset acc ----
        if ((c & 15) == 15) {
            const int k0 = (c >> 4) << 7;
            const int slot = warp_n * 4 + tig;
            #pragma unroll
            for (int m = 0; m < 4; m++) {
                #pragma unroll
                for (int p = 0; p < 2; p++) {
                    const int t_loc = tbase + m * 16 + gid + p * 8;
                    float mv = 3.4e38f; int mi = 0;
                    #pragma unroll
                    for (int n = 0; n < 4; n++) {      // ascending k
                        const int k = k0 + wbase + n * 8 + 2 * tig;
                        float se = __ldg(&g_csq[k])     - 2.f * acc[m][n][p * 2];
                        float so = __ldg(&g_csq[k + 1]) - 2.f * acc[m][n][p * 2 + 1];
                        if (se < mv) { mv = se; mi = k; }       // strict <
                        if (so < mv) { mv = so; mi = k + 1; }
                    }
                    redv[slot * 128 + t_loc] = mv;
                    redi[slot * 128 + t_loc] = mi;
                }
            }
            #pragma unroll
            for (int m = 0; m < 4; m++)
                #pragma unroll
                for (int n = 0; n < 4; n++)
                    #pragma unroll
                    for (int r = 0; r < 4; r++) acc[m][n][r] = 0.f;
            __syncthreads();
            if (tid < TILE_T) {
                float mv = bestv[tid]; int mi = besti[tid];
                #pragma unroll
                for (int r = 0; r < 16; r++) {
                    float v = redv[r * 128 + tid]; int ii = redi[r * 128 + tid];
                    if (v < mv || (v == mv && ii < mi)) { mv = v; mi = ii; }
                }
                bestv[tid] = mv; besti[tid] = mi;
            }
        }
        __syncthreads();
    }

    // ---- outputs ----
    if (tid < TILE_T) iout[(size_t)b * TT + t0 + tid] = (float)besti[tid];
    __syncthreads();

    float* qb = qout + (size_t)b * DD * TT + t0;
    for (int e = tid; e < DD * TILE_T; e += 256) {
        int t = e & (TILE_T - 1);
        int d = e >> 7;
        qb[(size_t)d * TT + t] = cb[(size_t)besti[t] * DD + d];
    }
}

extern "C" void kernel_launch(void* const* d_in, const int* in_sizes, int n_in,
                              void* d_out, int out_size) {
    const float* x  = (const float*)d_in[0];   // [B, D, T] fp32
    const float* cb = (const float*)d_in[1];   // [K, D]    fp32

    float* qout = (float*)d_out;                         // [B, D, T]
    float* iout = (float*)d_out + (size_t)BB * DD * TT;  // [B, T] as float

    cudaFuncSetAttribute(vq_kernel, cudaFuncAttributeMaxDynamicSharedMemorySize,
                         SMEM_BYTES);

    csq_kernel<<<(KK * 32 + 255) / 256, 256>>>(cb);
    vq_kernel<<<(BB * TT) / TILE_T, 256, SMEM_BYTES>>>(x, cb, qout, iout);
}

// round 8
// speedup vs baseline: 2.2310x; 1.6468x over previous
#include <cuda_runtime.h>
#include <cuda_bf16.h>
#include <cstdint>

#define BB 16
#define DD 512
#define TT 4096
#define KK 1024

#define TILE_T 128
#define TILE_K 128
#define TILE_D 32
#define N_CHUNKS ((KK / TILE_K) * (DD / TILE_D))   // 128
#define XS_STRIDE 136
#define XS_FL (TILE_D * XS_STRIDE)     // 4352 floats per stage
#define CS_ROW 36
#define CS_FL (TILE_K * CS_ROW)        // 4608 floats per stage

// ---- dynamic smem layout (float offsets) ----
#define F_XS    0                      // 2 x 4352 = 8704
#define F_CS    8704                   // 2 x 4608 = 9216
#define F_RV1   17920                  // 2048
#define F_RI1   19968                  // 2048
#define F_RV2   22016                  // 2048
#define F_RI2   24064                  // 2048
#define F_BV1   26112                  // 128
#define F_BI1   26240                  // 128
#define F_BV2   26368                  // 128
#define F_BI2   26496                  // 128
#define SMEM_FLOATS 26624
#define SMEM_BYTES  (SMEM_FLOATS * 4)  // 106496 B -> occ 2

__device__ float g_csq[KK];
__device__ float g_xr[(size_t)BB * DD * TT];   // tf32-rounded x (134 MB scratch)
__device__ float g_cbr[KK * DD];               // tf32-rounded codebook

// ---------------- helpers ----------------
__device__ __forceinline__ uint32_t smem_u32(const void* p) {
    uint32_t a;
    asm("{ .reg .u64 t; cvta.to.shared.u64 t, %1; cvt.u32.u64 %0, t; }" : "=r"(a) : "l"(p));
    return a;
}
__device__ __forceinline__ void cp16(uint32_t dst, const void* src) {
    asm volatile("cp.async.cg.shared.global [%0], [%1], 16;" :: "r"(dst), "l"(src));
}
#define CP_COMMIT() asm volatile("cp.async.commit_group;" ::: "memory")
#define CP_WAIT1()  asm volatile("cp.async.wait_group 1;" ::: "memory")
#define CP_WAIT0()  asm volatile("cp.async.wait_group 0;" ::: "memory")

__device__ __forceinline__ float tf32r(float v) {
    uint32_t r; asm("cvt.rna.tf32.f32 %0, %1;" : "=r"(r) : "f"(v));
    return __uint_as_float(r);
}
// D(16x8,f32) += A(16x8 tf32, row) * B(8x8 tf32, col)
__device__ __forceinline__ void mma_tf32(float* d, const uint32_t* a, const uint32_t* b) {
    asm volatile(
        "mma.sync.aligned.m16n8k8.row.col.f32.tf32.tf32.f32 "
        "{%0,%1,%2,%3}, {%4,%5,%6,%7}, {%8,%9}, {%0,%1,%2,%3};"
        : "+f"(d[0]), "+f"(d[1]), "+f"(d[2]), "+f"(d[3])
        : "r"(a[0]), "r"(a[1]), "r"(a[2]), "r"(a[3]), "r"(b[0]), "r"(b[1]));
}
// top-2 update with jnp tie-break (lowest index wins on equal value)
__device__ __forceinline__ void top2(float v, int i, float& v1, int& i1,
                                     float& v2, int& i2) {
    if (v < v1 || (v == v1 && i < i1)) { v2 = v1; i2 = i1; v1 = v; i1 = i; }
    else if (v < v2 || (v == v2 && i < i2)) { v2 = v; i2 = i; }
}

// ---------------------------------------------------------------------------
__global__ void csq_kernel(const float* __restrict__ cb) {
    int warp = (blockIdx.x * blockDim.x + threadIdx.x) >> 5;
    int lane = threadIdx.x & 31;
    if (warp < KK) {
        const float* row = cb + (size_t)warp * DD;
        float s = 0.f;
        #pragma unroll
        for (int d = lane; d < DD; d += 32) { float v = row[d]; s += v * v; }
        #pragma unroll
        for (int o = 16; o; o >>= 1) s += __shfl_xor_sync(0xFFFFFFFFu, s, o);
        if (lane == 0) g_csq[warp] = s;
    }
}

// elementwise tf32 rounding into scratch (removes all cvt from the hot loop)
__global__ void prep_round(const float* __restrict__ src, float* __restrict__ dst,
                           int n4) {
    int i = blockIdx.x * blockDim.x + threadIdx.x;
    if (i < n4) {
        float4 v = ((const float4*)src)[i];
        v.x = tf32r(v.x); v.y = tf32r(v.y); v.z = tf32r(v.z); v.w = tf32r(v.w);
        ((float4*)dst)[i] = v;
    }
}

// ---------------------------------------------------------------------------
// Single-pass tf32 HMMA screen -> top-2 -> exact fp32 rescore -> gather.
// 256 threads = 8 warps: 2(m:t) x 4(n:k); warp tile 64t x 32k.
// ---------------------------------------------------------------------------
__global__ __launch_bounds__(256, 2)
void vq_kernel(const float* __restrict__ x, const float* __restrict__ cb,
               float* __restrict__ qout, float* __restrict__ iout) {
    extern __shared__ float sm[];
    float* XS  = sm + F_XS;
    float* CS  = sm + F_CS;
    float* rv1 = sm + F_RV1;  int* ri1 = (int*)(sm + F_RI1);
    float* rv2 = sm + F_RV2;  int* ri2 = (int*)(sm + F_RI2);
    float* bv1 = sm + F_BV1;  int* bi1 = (int*)(sm + F_BI1);
    float* bv2 = sm + F_BV2;  int* bi2 = (int*)(sm + F_BI2);

    const int tid    = threadIdx.x;
    const int wid    = tid >> 5;
    const int lane   = tid & 31;
    const int gid    = lane >> 2;
    const int tig    = lane & 3;
    const int warp_m = wid >> 2;
    const int warp_n = wid & 3;
    const int tbase  = warp_m * 64;
    const int wbase  = warp_n * 32;

    const int blk = blockIdx.x;
    const int b   = blk >> 5;
    const int t0  = (blk & 31) << 7;

    const float* xb  = x + (size_t)b * DD * TT + t0;       // raw (rescore)
    const float* xrb = g_xr + (size_t)b * DD * TT + t0;    // rounded (screen)

    const uint32_t xs_u = smem_u32(XS);
    const uint32_t cs_u = smem_u32(CS);

    if (tid < TILE_T) { bv1[tid] = 3.4e38f; bi1[tid] = 0;
                        bv2[tid] = 3.4e38f; bi2[tid] = 0; }

    auto issue = [&](int c, int s) {
        const int k0 = (c >> 4) << 7;
        const int d0 = (c & 15) << 5;
        const uint32_t xdst = xs_u + (uint32_t)(s * XS_FL * 4);
        const uint32_t cdst = cs_u + (uint32_t)(s * CS_FL * 4);
        #pragma unroll
        for (int l = 0; l < 4; l++) {            // x: 32d x 128t (rounded)
            int e  = l * 256 + tid;
            int d  = e >> 5;
            int t4 = e & 31;
            cp16(xdst + (uint32_t)((d * XS_STRIDE + t4 * 4) * 4),
                 xrb + (size_t)(d0 + d) * TT + t4 * 4);
        }
        #pragma unroll
        for (int l = 0; l < 4; l++) {            // cb: 128k x 32d (rounded)
            int e  = l * 256 + tid;
            int k  = e >> 3;
            int dq = e & 7;
            cp16(cdst + (uint32_t)((k * CS_ROW + dq * 4) * 4),
                 g_cbr + (size_t)(k0 + k) * DD + d0 + dq * 4);
        }
        CP_COMMIT();
    };

    float acc[4][4][4];
    #pragma unroll
    for (int m = 0; m < 4; m++)
        #pragma unroll
        for (int n = 0; n < 4; n++)
            #pragma unroll
            for (int r = 0; r < 4; r++) acc[m][n][r] = 0.f;

    issue(0, 0);

    for (int c = 0; c < N_CHUNKS; c++) {
        const int s = c & 1;
        if (c + 1 < N_CHUNKS) issue(c + 1, s ^ 1);
        if (c + 1 < N_CHUNKS) { CP_WAIT1(); } else { CP_WAIT0(); }
        __syncthreads();

        const float* xsS = XS + s * XS_FL;
        const float* csS = CS + s * CS_FL;

        #pragma unroll
        for (int ds = 0; ds < 4; ds++) {
            const int dA = ds * 8 + tig;
            uint32_t ah[4][4];
            #pragma unroll
            for (int m = 0; m < 4; m++) {
                const int t = tbase + m * 16 + gid;
                ah[m][0] = __float_as_uint(xsS[dA * XS_STRIDE + t]);
                ah[m][1] = __float_as_uint(xsS[dA * XS_STRIDE + t + 8]);
                ah[m][2] = __float_as_uint(xsS[(dA + 4) * XS_STRIDE + t]);
                ah[m][3] = __float_as_uint(xsS[(dA + 4) * XS_STRIDE + t + 8]);
            }
            #pragma unroll
            for (int n = 0; n < 4; n++) {
                const int kr = wbase + n * 8 + gid;
                uint32_t bh[2];
                bh[0] = __float_as_uint(csS[kr * CS_ROW + ds * 8 + tig]);
                bh[1] = __float_as_uint(csS[kr * CS_ROW + ds * 8 + tig + 4]);
                #pragma unroll
                for (int m = 0; m < 4; m++) mma_tf32(acc[m][n], ah[m], bh);
            }
        }

        // ---- end of a k-pass: fold top-2, merge, reset acc ----
        if ((c & 15) == 15) {
            const int k0 = (c >> 4) << 7;
            const int slot = warp_n * 4 + tig;
            #pragma unroll
            for (int m = 0; m < 4; m++) {
                #pragma unroll
                for (int p = 0; p < 2; p++) {
                    const int t_loc = tbase + m * 16 + gid + p * 8;
                    float v1 = 3.4e38f, v2 = 3.4e38f;
                    int   i1 = 0,       i2 = 0;
                    #pragma unroll
                    for (int n = 0; n < 4; n++) {
                        const int k = k0 + wbase + n * 8 + 2 * tig;
                        float se = __ldg(&g_csq[k])     - 2.f * acc[m][n][p * 2];
                        float so = __ldg(&g_csq[k + 1]) - 2.f * acc[m][n][p * 2 + 1];
                        top2(se, k,     v1, i1, v2, i2);
                        top2(so, k + 1, v1, i1, v2, i2);
                    }
                    rv1[slot * 128 + t_loc] = v1; ri1[slot * 128 + t_loc] = i1;
                    rv2[slot * 128 + t_loc] = v2; ri2[slot * 128 + t_loc] = i2;
                }
            }
            #pragma unroll
            for (int m = 0; m < 4; m++)
                #pragma unroll
                for (int n = 0; n < 4; n++)
                    #pragma unroll
                    for (int r = 0; r < 4; r++) acc[m][n][r] = 0.f;
            __syncthreads();
            if (tid < TILE_T) {
                float v1 = bv1[tid], v2 = bv2[tid];
                int   i1 = bi1[tid], i2 = bi2[tid];
                #pragma unroll
                for (int r = 0; r < 16; r++) {
                    top2(rv1[r * 128 + tid], ri1[r * 128 + tid], v1, i1, v2, i2);
                    top2(rv2[r * 128 + tid], ri2[r * 128 + tid], v1, i1, v2, i2);
                }
                bv1[tid] = v1; bi1[tid] = i1; bv2[tid] = v2; bi2[tid] = i2;
            }
        }
        __syncthreads();
    }

    // ---- exact fp32 rescore of top-2 candidates (raw x, raw cb) ----
    const int p    = tid >> 1;
    const int half = tid & 1;
    const int cand = half ? bi2[p] : bi1[p];
    const float* crow = cb + (size_t)cand * DD;
    float dot = 0.f;
    for (int dc = 0; dc < 16; dc++) {
        const int d0 = dc * 32;
        __syncthreads();
        #pragma unroll
        for (int l = 0; l < 4; l++) {
            int e  = l * 256 + tid;
            int d  = e >> 5;
            int t4 = e & 31;
            *(float4*)&XS[d * XS_STRIDE + t4 * 4] =
                *(const float4*)(xb + (size_t)(d0 + d) * TT + t4 * 4);
        }
        __syncthreads();
        #pragma unroll
        for (int j = 0; j < 8; j++) {
            float4 cv = *(const float4*)(crow + d0 + 4 * j);
            dot = fmaf(XS[(4 * j + 0) * XS_STRIDE + p], cv.x, dot);
            dot = fmaf(XS[(4 * j + 1) * XS_STRIDE + p], cv.y, dot);
            dot = fmaf(XS[(4 * j + 2) * XS_STRIDE + p], cv.z, dot);
            dot = fmaf(XS[(4 * j + 3) * XS_STRIDE + p], cv.w, dot);
        }
    }
    rv1[tid] = __ldg(&g_csq[cand]) - 2.f * dot;
    __syncthreads();
    if (tid < TILE_T) {
        float sA = rv1[2 * tid], sB = rv1[2 * tid + 1];
        int   iA = bi1[tid],     iB = bi2[tid];
        int fin = (sB < sA || (sB == sA && iB < iA)) ? iB : iA;
        bi1[tid] = fin;
        iout[(size_t)b * TT + t0 + tid] = (float)fin;
    }
    __syncthreads();

    // ---- gather quantized: t-coalesced stores ----
    float* qb = qout + (size_t)b * DD * TT + t0;
    for (int e = tid; e < DD * TILE_T; e += 256) {
        int t = e & (TILE_T - 1);
        int d = e >> 7;
        qb[(size_t)d * TT + t] = cb[(size_t)bi1[t] * DD + d];
    }
}

extern "C" void kernel_launch(void* const* d_in, const int* in_sizes, int n_in,
                              void* d_out, int out_size) {
    const float* x  = (const float*)d_in[0];   // [B, D, T] fp32
    const float* cb = (const float*)d_in[1];   // [K, D]    fp32

    float* qout = (float*)d_out;                         // [B, D, T]
    float* iout = (float*)d_out + (size_t)BB * DD * TT;  // [B, T] as float

    cudaFuncSetAttribute(vq_kernel, cudaFuncAttributeMaxDynamicSharedMemorySize,
                         SMEM_BYTES);

    float* xr;  cudaGetSymbolAddress((void**)&xr,  g_xr);
    float* cbr; cudaGetSymbolAddress((void**)&cbr, g_cbr);

    csq_kernel<<<(KK * 32 + 255) / 256, 256>>>(cb);
    {
        int n4 = (BB * DD * TT) / 4;
        prep_round<<<(n4 + 255) / 256, 256>>>(x, xr, n4);
    }
    {
        int n4 = (KK * DD) / 4;
        prep_round<<<(n4 + 255) / 256, 256>>>(cb, cbr, n4);
    }
    vq_kernel<<<(BB * TT) / TILE_T, 256, SMEM_BYTES>>>(x, cb, qout, iout);
}

// round 9
// speedup vs baseline: 2.3086x; 1.0348x over previous
#include <cuda_runtime.h>
#include <cuda_bf16.h>
#include <cstdint>

#define BB 16
#define DD 512
#define TT 4096
#define KK 1024

#define TILE_T 128
#define TILE_K 128
#define TILE_D 32
#define N_CHUNKS ((KK / TILE_K) * (DD / TILE_D))   // 128
#define XS_STRIDE 136
#define XS_FL (TILE_D * XS_STRIDE)     // 4352 floats per stage
#define CS_ROW 36
#define CS_FL (TILE_K * CS_ROW)        // 4608 floats per stage

// ---- dynamic smem layout (float offsets) ----
#define F_XS    0                      // 2 x 4352 = 8704
#define F_CS    8704                   // 2 x 4608 = 9216
#define F_RV1   17920                  // 2048
#define F_RI1   19968                  // 2048
#define F_RV2   22016                  // 2048
#define F_RI2   24064                  // 2048
#define F_BV1   26112                  // 128
#define F_BI1   26240                  // 128
#define F_BV2   26368                  // 128
#define F_BI2   26496                  // 128
#define SMEM_FLOATS 26624
#define SMEM_BYTES  (SMEM_FLOATS * 4)  // 106496 B -> occ 2

__device__ float g_csq[KK];
__device__ float g_xr[(size_t)BB * DD * TT];   // tf32-rounded x
__device__ float g_cbr[KK * DD];               // tf32-rounded codebook

// ---------------- helpers ----------------
__device__ __forceinline__ uint32_t smem_u32(const void* p) {
    uint32_t a;
    asm("{ .reg .u64 t; cvta.to.shared.u64 t, %1; cvt.u32.u64 %0, t; }" : "=r"(a) : "l"(p));
    return a;
}
__device__ __forceinline__ void cp16(uint32_t dst, const void* src) {
    asm volatile("cp.async.cg.shared.global [%0], [%1], 16;" :: "r"(dst), "l"(src));
}
#define CP_COMMIT() asm volatile("cp.async.commit_group;" ::: "memory")
#define CP_WAIT1()  asm volatile("cp.async.wait_group 1;" ::: "memory")
#define CP_WAIT0()  asm volatile("cp.async.wait_group 0;" ::: "memory")

__device__ __forceinline__ float tf32r(float v) {
    uint32_t r; asm("cvt.rna.tf32.f32 %0, %1;" : "=r"(r) : "f"(v));
    return __uint_as_float(r);
}
// 8x8 b16 ldmatrix x4 == four 8x4 b32 tiles; lane l of each tile gets (l/4, l%4)
__device__ __forceinline__ void ldsm4(uint32_t* r, uint32_t addr) {
    asm volatile("ldmatrix.sync.aligned.m8n8.x4.shared.b16 {%0,%1,%2,%3}, [%4];"
                 : "=r"(r[0]), "=r"(r[1]), "=r"(r[2]), "=r"(r[3]) : "r"(addr));
}
// D(16x8,f32) += A(16x8 tf32, row) * B(8x8 tf32, col)
__device__ __forceinline__ void mma_tf32(float* d, const uint32_t* a, const uint32_t* b) {
    asm volatile(
        "mma.sync.aligned.m16n8k8.row.col.f32.tf32.tf32.f32 "
        "{%0,%1,%2,%3}, {%4,%5,%6,%7}, {%8,%9}, {%0,%1,%2,%3};"
        : "+f"(d[0]), "+f"(d[1]), "+f"(d[2]), "+f"(d[3])
        : "r"(a[0]), "r"(a[1]), "r"(a[2]), "r"(a[3]), "r"(b[0]), "r"(b[1]));
}
// top-2 update with jnp tie-break (lowest index wins on equal value)
__device__ __forceinline__ void top2(float v, int i, float& v1, int& i1,
                                     float& v2, int& i2) {
    if (v < v1 || (v == v1 && i < i1)) { v2 = v1; i2 = i1; v1 = v; i1 = i; }
    else if (v < v2 || (v == v2 && i < i2)) { v2 = v; i2 = i; }
}

// ---------------------------------------------------------------------------
__global__ void csq_kernel(const float* __restrict__ cb) {
    int warp = (blockIdx.x * blockDim.x + threadIdx.x) >> 5;
    int lane = threadIdx.x & 31;
    if (warp < KK) {
        const float* row = cb + (size_t)warp * DD;
        float s = 0.f;
        #pragma unroll
        for (int d = lane; d < DD; d += 32) { float v = row[d]; s += v * v; }
        #pragma unroll
        for (int o = 16; o; o >>= 1) s += __shfl_xor_sync(0xFFFFFFFFu, s, o);
        if (lane == 0) g_csq[warp] = s;
    }
}

__global__ void prep_round(const float* __restrict__ src, float* __restrict__ dst,
                           int n4) {
    int i = blockIdx.x * blockDim.x + threadIdx.x;
    if (i < n4) {
        float4 v = ((const float4*)src)[i];
        v.x = tf32r(v.x); v.y = tf32r(v.y); v.z = tf32r(v.z); v.w = tf32r(v.w);
        ((float4*)dst)[i] = v;
    }
}

// ---------------------------------------------------------------------------
// Swapped-operand tf32 screen: A = codebook (ldmatrix), B = x (scalar LDS).
// 8 warps: warp_k = wid>>2 (2 x 64k), warp_t = wid&3 (4 x 32t).
// acc[m][n]: rows = k (16 per m-tile), cols = t (8 per n-tile).
// ---------------------------------------------------------------------------
__global__ __launch_bounds__(256, 2)
void vq_kernel(const float* __restrict__ x, const float* __restrict__ cb,
               float* __restrict__ qout, float* __restrict__ iout) {
    extern __shared__ float sm[];
    float* XS  = sm + F_XS;
    float* CS  = sm + F_CS;
    float* rv1 = sm + F_RV1;  int* ri1 = (int*)(sm + F_RI1);
    float* rv2 = sm + F_RV2;  int* ri2 = (int*)(sm + F_RI2);
    float* bv1 = sm + F_BV1;  int* bi1 = (int*)(sm + F_BI1);
    float* bv2 = sm + F_BV2;  int* bi2 = (int*)(sm + F_BI2);

    const int tid    = threadIdx.x;
    const int wid    = tid >> 5;
    const int lane   = tid & 31;
    const int gid    = lane >> 2;       // 0..7
    const int tig    = lane & 3;        // 0..3
    const int warp_k = wid >> 2;        // 0..1 (64 k each)
    const int warp_t = wid & 3;         // 0..3 (32 t each)
    const int kwb    = warp_k * 64;
    const int twb    = warp_t * 32;
    // ldmatrix per-lane row mapping: k-row = lane&15, d-col half = (lane&16)? +4
    const int lm_k  = lane & 15;
    const int lm_d4 = (lane & 16) >> 2;

    const int blk = blockIdx.x;
    const int b   = blk >> 5;
    const int t0  = (blk & 31) << 7;

    const float* xb  = x + (size_t)b * DD * TT + t0;       // raw (rescore)
    const float* xrb = g_xr + (size_t)b * DD * TT + t0;    // rounded (screen)

    const uint32_t xs_u = smem_u32(XS);
    const uint32_t cs_u = smem_u32(CS);

    if (tid < TILE_T) { bv1[tid] = 3.4e38f; bi1[tid] = 0;
                        bv2[tid] = 3.4e38f; bi2[tid] = 0; }

    auto issue = [&](int c, int s) {
        const int k0 = (c >> 4) << 7;
        const int d0 = (c & 15) << 5;
        const uint32_t xdst = xs_u + (uint32_t)(s * XS_FL * 4);
        const uint32_t cdst = cs_u + (uint32_t)(s * CS_FL * 4);
        #pragma unroll
        for (int l = 0; l < 4; l++) {            // x: 32d x 128t (rounded)
            int e  = l * 256 + tid;
            int d  = e >> 5;
            int t4 = e & 31;
            cp16(xdst + (uint32_t)((d * XS_STRIDE + t4 * 4) * 4),
                 xrb + (size_t)(d0 + d) * TT + t4 * 4);
        }
        #pragma unroll
        for (int l = 0; l < 4; l++) {            // cb: 128k x 32d (rounded)
            int e  = l * 256 + tid;
            int k  = e >> 3;
            int dq = e & 7;
            cp16(cdst + (uint32_t)((k * CS_ROW + dq * 4) * 4),
                 g_cbr + (size_t)(k0 + k) * DD + d0 + dq * 4);
        }
        CP_COMMIT();
    };

    float acc[4][4][4];
    #pragma unroll
    for (int m = 0; m < 4; m++)
        #pragma unroll
        for (int n = 0; n < 4; n++)
            #pragma unroll
            for (int r = 0; r < 4; r++) acc[m][n][r] = 0.f;

    issue(0, 0);

    for (int c = 0; c < N_CHUNKS; c++) {
        const int s = c & 1;
        if (c + 1 < N_CHUNKS) issue(c + 1, s ^ 1);
        if (c + 1 < N_CHUNKS) { CP_WAIT1(); } else { CP_WAIT0(); }
        __syncthreads();

        const float* xsS = XS + s * XS_FL;
        const uint32_t csS_u = cs_u + (uint32_t)(s * CS_FL * 4);

        #pragma unroll
        for (int ds = 0; ds < 4; ds++) {
            // A fragments: codebook, 4 k-tiles of 16, via ldmatrix.x4
            uint32_t af[4][4];
            #pragma unroll
            for (int m = 0; m < 4; m++) {
                uint32_t addr = csS_u +
                    (uint32_t)(((kwb + m * 16 + lm_k) * CS_ROW + ds * 8 + lm_d4) * 4);
                ldsm4(af[m], addr);
            }
            // B fragments: x, 4 t-tiles of 8, 2 scalar LDS each
            #pragma unroll
            for (int n = 0; n < 4; n++) {
                const int tcol = twb + n * 8 + gid;
                uint32_t bf[2];
                bf[0] = __float_as_uint(xsS[(ds * 8 + tig) * XS_STRIDE + tcol]);
                bf[1] = __float_as_uint(xsS[(ds * 8 + tig + 4) * XS_STRIDE + tcol]);
                #pragma unroll
                for (int m = 0; m < 4; m++) mma_tf32(acc[m][n], af[m], bf);
            }
        }

        // ---- end of a k-pass: fold top-2 (rows=k, cols=t), merge, reset ----
        if ((c & 15) == 15) {
            const int k0p  = (c >> 4) << 7;
            const int slot = warp_k * 8 + gid;
            const int kb   = k0p + kwb;
            #pragma unroll
            for (int n = 0; n < 4; n++) {
                const int te = twb + n * 8 + 2 * tig;
                float v1e = 3.4e38f, v2e = 3.4e38f; int i1e = 0, i2e = 0;
                float v1o = 3.4e38f, v2o = 3.4e38f; int i1o = 0, i2o = 0;
                #pragma unroll
                for (int m = 0; m < 4; m++) {
                    const int kA = kb + m * 16 + gid;
                    const float cqA = __ldg(&g_csq[kA]);
                    const float cqB = __ldg(&g_csq[kA + 8]);
                    top2(cqA - 2.f * acc[m][n][0], kA,     v1e, i1e, v2e, i2e);
                    top2(cqB - 2.f * acc[m][n][2], kA + 8, v1e, i1e, v2e, i2e);
                    top2(cqA - 2.f * acc[m][n][1], kA,     v1o, i1o, v2o, i2o);
                    top2(cqB - 2.f * acc[m][n][3], kA + 8, v1o, i1o, v2o, i2o);
                }
                rv1[slot * 128 + te] = v1e;     ri1[slot * 128 + te] = i1e;
                rv2[slot * 128 + te] = v2e;     ri2[slot * 128 + te] = i2e;
                rv1[slot * 128 + te + 1] = v1o; ri1[slot * 128 + te + 1] = i1o;
                rv2[slot * 128 + te + 1] = v2o; ri2[slot * 128 + te + 1] = i2o;
            }
            #pragma unroll
            for (int m = 0; m < 4; m++)
                #pragma unroll
                for (int n = 0; n < 4; n++)
                    #pragma unroll
                    for (int r = 0; r < 4; r++) acc[m][n][r] = 0.f;
            __syncthreads();
            if (tid < TILE_T) {
                float v1 = bv1[tid], v2 = bv2[tid];
                int   i1 = bi1[tid], i2 = bi2[tid];
                #pragma unroll
                for (int r = 0; r < 16; r++) {
                    top2(rv1[r * 128 + tid], ri1[r * 128 + tid], v1, i1, v2, i2);
                    top2(rv2[r * 128 + tid], ri2[r * 128 + tid], v1, i1, v2, i2);
                }
                bv1[tid] = v1; bi1[tid] = i1; bv2[tid] = v2; bi2[tid] = i2;
            }
        }
        __syncthreads();
    }

    // ---- exact fp32 rescore of top-2 candidates (raw x, raw cb) ----
    const int p    = tid >> 1;
    const int half = tid & 1;
    const int cand = half ? bi2[p] : bi1[p];
    const float* crow = cb + (size_t)cand * DD;
    float dot = 0.f;
    for (int dc = 0; dc < 16; dc++) {
        const int d0 = dc * 32;
        __syncthreads();
        #pragma unroll
        for (int l = 0; l < 4; l++) {
            int e  = l * 256 + tid;
            int d  = e >> 5;
            int t4 = e & 31;
            *(float4*)&XS[d * XS_STRIDE + t4 * 4] =
                *(const float4*)(xb + (size_t)(d0 + d) * TT + t4 * 4);
        }
        __syncthreads();
        #pragma unroll
        for (int j = 0; j < 8; j++) {
            float4 cv = *(const float4*)(crow + d0 + 4 * j);
            dot = fmaf(XS[(4 * j + 0) * XS_STRIDE + p], cv.x, dot);
            dot = fmaf(XS[(4 * j + 1) * XS_STRIDE + p], cv.y, dot);
            dot = fmaf(XS[(4 * j + 2) * XS_STRIDE + p], cv.z, dot);
            dot = fmaf(XS[(4 * j + 3) * XS_STRIDE + p], cv.w, dot);
        }
    }
    rv1[tid] = __ldg(&g_csq[cand]) - 2.f * dot;
    __syncthreads();
    if (tid < TILE_T) {
        float sA = rv1[2 * tid], sB = rv1[2 * tid + 1];
        int   iA = bi1[tid],     iB = bi2[tid];
        int fin = (sB < sA || (sB == sA && iB < iA)) ? iB : iA;
        bi1[tid] = fin;
        iout[(size_t)b * TT + t0 + tid] = (float)fin;
    }
    __syncthreads();

    // ---- gather quantized: t-coalesced stores ----
    float* qb = qout + (size_t)b * DD * TT + t0;
    for (int e = tid; e < DD * TILE_T; e += 256) {
        int t = e & (TILE_T - 1);
        int d = e >> 7;
        qb[(size_t)d * TT + t] = cb[(size_t)bi1[t] * DD + d];
    }
}

extern "C" void kernel_launch(void* const* d_in, const int* in_sizes, int n_in,
                              void* d_out, int out_size) {
    const float* x  = (const float*)d_in[0];   // [B, D, T] fp32
    const float* cb = (const float*)d_in[1];   // [K, D]    fp32

    float* qout = (float*)d_out;                         // [B, D, T]
    float* iout = (float*)d_out + (size_t)BB * DD * TT;  // [B, T] as float

    cudaFuncSetAttribute(vq_kernel, cudaFuncAttributeMaxDynamicSharedMemorySize,
                         SMEM_BYTES);

    float* xr;  cudaGetSymbolAddress((void**)&xr,  g_xr);
    float* cbr; cudaGetSymbolAddress((void**)&cbr, g_cbr);

    csq_kernel<<<(KK * 32 + 255) / 256, 256>>>(cb);
    {
        int n4 = (BB * DD * TT) / 4;
        prep_round<<<(n4 + 255) / 256, 256>>>(x, xr, n4);
    }
    {
        int n4 = (KK * DD) / 4;
        prep_round<<<(n4 + 255) / 256, 256>>>(cb, cbr, n4);
    }
    vq_kernel<<<(BB * TT) / TILE_T, 256, SMEM_BYTES>>>(x, cb, qout, iout);
}

// round 10
// speedup vs baseline: 3.1094x; 1.3469x over previous
#include <cuda_runtime.h>
#include <cuda_fp16.h>
#include <cstdint>

#define BB 16
#define DD 512
#define TT 4096
#define KK 1024

#define TILE_T 128
#define TILE_K 128
#define TILE_D 32
#define N_CHUNKS 128

#define XROWH 136                      // x tile row stride (halfs)
#define CROWH 40                       // cb tile row stride (halfs)
#define XS_STG (TILE_D * XROWH * 2)    // 8704 B per stage
#define CS_STG (TILE_K * CROWH * 2)    // 10240 B per stage

// ---- dynamic smem layout (byte offsets) ----
#define B_XS   0                       // 2 x 8704  = 17408
#define B_CS   17408                   // 2 x 10240 = 20480 -> 37888
#define B_RV1  37888                   // 16x128 f32 = 8192
#define B_RI1  46080
#define B_RV2  54272
#define B_RI2  62464
#define B_BV1  70656                   // 128 f32
#define B_BI1  71168
#define B_BV2  71680
#define B_BI2  72192
#define SMEM_BYTES 72704

#define XS_STRIDE 136                  // rescore float staging stride

__device__ float  g_csq[KK];
__device__ __half g_xh[(size_t)BB * DD * TT];   // fp16 x (67 MB scratch)
__device__ __half g_cbh[KK * DD];               // fp16 codebook

// ---------------- helpers ----------------
__device__ __forceinline__ uint32_t smem_u32(const void* p) {
    uint32_t a;
    asm("{ .reg .u64 t; cvta.to.shared.u64 t, %1; cvt.u32.u64 %0, t; }" : "=r"(a) : "l"(p));
    return a;
}
__device__ __forceinline__ void cp16(uint32_t dst, const void* src) {
    asm volatile("cp.async.cg.shared.global [%0], [%1], 16;" :: "r"(dst), "l"(src));
}
#define CP_COMMIT() asm volatile("cp.async.commit_group;" ::: "memory")
#define CP_WAIT1()  asm volatile("cp.async.wait_group 1;" ::: "memory")
#define CP_WAIT0()  asm volatile("cp.async.wait_group 0;" ::: "memory")

__device__ __forceinline__ void ldsm4(uint32_t* r, uint32_t addr) {
    asm volatile("ldmatrix.sync.aligned.m8n8.x4.shared.b16 {%0,%1,%2,%3}, [%4];"
                 : "=r"(r[0]), "=r"(r[1]), "=r"(r[2]), "=r"(r[3]) : "r"(addr));
}
__device__ __forceinline__ void ldsm2t(uint32_t* r, uint32_t addr) {
    asm volatile("ldmatrix.sync.aligned.m8n8.x2.trans.shared.b16 {%0,%1}, [%2];"
                 : "=r"(r[0]), "=r"(r[1]) : "r"(addr));
}
// D(16x8,f32) += A(16x16 f16) * B(16x8 f16)
__device__ __forceinline__ void mma_f16(float* d, const uint32_t* a, const uint32_t* b) {
    asm volatile(
        "mma.sync.aligned.m16n8k16.row.col.f32.f16.f16.f32 "
        "{%0,%1,%2,%3}, {%4,%5,%6,%7}, {%8,%9}, {%0,%1,%2,%3};"
        : "+f"(d[0]), "+f"(d[1]), "+f"(d[2]), "+f"(d[3])
        : "r"(a[0]), "r"(a[1]), "r"(a[2]), "r"(a[3]), "r"(b[0]), "r"(b[1]));
}
// top-2 update with jnp tie-break (lowest index wins on equal value)
__device__ __forceinline__ void top2(float v, int i, float& v1, int& i1,
                                     float& v2, int& i2) {
    if (v < v1 || (v == v1 && i < i1)) { v2 = v1; i2 = i1; v1 = v; i1 = i; }
    else if (v < v2 || (v == v2 && i < i2)) { v2 = v; i2 = i; }
}

// ---------------------------------------------------------------------------
__global__ void csq_kernel(const float* __restrict__ cb) {
    int warp = (blockIdx.x * blockDim.x + threadIdx.x) >> 5;
    int lane = threadIdx.x & 31;
    if (warp < KK) {
        const float* row = cb + (size_t)warp * DD;
        float s = 0.f;
        #pragma unroll
        for (int d = lane; d < DD; d += 32) { float v = row[d]; s += v * v; }
        #pragma unroll
        for (int o = 16; o; o >>= 1) s += __shfl_xor_sync(0xFFFFFFFFu, s, o);
        if (lane == 0) g_csq[warp] = s;
    }
}

// f32 -> fp16 conversion, 8 elems/thread
__global__ void prep_half(const float* __restrict__ src, __half* __restrict__ dst,
                          int n8) {
    int i = blockIdx.x * blockDim.x + threadIdx.x;
    if (i < n8) {
        float4 a = ((const float4*)src)[2 * i];
        float4 b = ((const float4*)src)[2 * i + 1];
        __half2 h0 = __floats2half2_rn(a.x, a.y);
        __half2 h1 = __floats2half2_rn(a.z, a.w);
        __half2 h2 = __floats2half2_rn(b.x, b.y);
        __half2 h3 = __floats2half2_rn(b.z, b.w);
        uint4 o;
        o.x = *(uint32_t*)&h0; o.y = *(uint32_t*)&h1;
        o.z = *(uint32_t*)&h2; o.w = *(uint32_t*)&h3;
        ((uint4*)dst)[i] = o;
    }
}

// ---------------------------------------------------------------------------
// fp16 HMMA screen (A = cb via ldmatrix.x4, B = x via ldmatrix.x2.trans)
// -> top-2 -> exact fp32 rescore -> gather.
// 8 warps: warp_k = wid>>2 (2 x 64k), warp_t = wid&3 (4 x 32t).
// ---------------------------------------------------------------------------
__global__ __launch_bounds__(256, 2)
void vq_kernel(const float* __restrict__ x, const float* __restrict__ cb,
               float* __restrict__ qout, float* __restrict__ iout) {
    extern __shared__ char smb[];
    float* rv1 = (float*)(smb + B_RV1);  int* ri1 = (int*)(smb + B_RI1);
    float* rv2 = (float*)(smb + B_RV2);  int* ri2 = (int*)(smb + B_RI2);
    float* bv1 = (float*)(smb + B_BV1);  int* bi1 = (int*)(smb + B_BI1);
    float* bv2 = (float*)(smb + B_BV2);  int* bi2 = (int*)(smb + B_BI2);

    const int tid    = threadIdx.x;
    const int wid    = tid >> 5;
    const int lane   = tid & 31;
    const int gid    = lane >> 2;
    const int tig    = lane & 3;
    const int warp_k = wid >> 2;
    const int warp_t = wid & 3;
    const int kwb    = warp_k * 64;
    const int twb    = warp_t * 32;
    const int lm_k   = lane & 15;
    const int lm_d8  = (lane & 16) >> 1;   // 0 or 8 (halfs)

    const int blk = blockIdx.x;
    const int b   = blk >> 5;
    const int t0  = (blk & 31) << 7;

    const float*  xb  = x + (size_t)b * DD * TT + t0;      // raw (rescore)
    const __half* xhb = g_xh + (size_t)b * DD * TT + t0;   // fp16 (screen)

    const uint32_t sb   = smem_u32(smb);
    const uint32_t xs_u = sb + B_XS;
    const uint32_t cs_u = sb + B_CS;

    if (tid < TILE_T) { bv1[tid] = 3.4e38f; bi1[tid] = 0;
                        bv2[tid] = 3.4e38f; bi2[tid] = 0; }

    auto issue = [&](int c, int s) {
        const int k0 = (c >> 4) << 7;
        const int d0 = (c & 15) << 5;
        const uint32_t xdst = xs_u + (uint32_t)(s * XS_STG);
        const uint32_t cdst = cs_u + (uint32_t)(s * CS_STG);
        #pragma unroll
        for (int l = 0; l < 2; l++) {            // x: 32d x 128t halfs
            int e  = l * 256 + tid;
            int d  = e >> 4;
            int t8 = e & 15;
            cp16(xdst + (uint32_t)((d * XROWH + t8 * 8) * 2),
                 xhb + (size_t)(d0 + d) * TT + t8 * 8);
        }
        #pragma unroll
        for (int l = 0; l < 2; l++) {            // cb: 128k x 32d halfs
            int e  = l * 256 + tid;
            int k  = e >> 2;
            int dq = e & 3;
            cp16(cdst + (uint32_t)((k * CROWH + dq * 8) * 2),
                 g_cbh + (size_t)(k0 + k) * DD + d0 + dq * 8);
        }
        CP_COMMIT();
    };

    float acc[4][4][4];
    #pragma unroll
    for (int m = 0; m < 4; m++)
        #pragma unroll
        for (int n = 0; n < 4; n++)
            #pragma unroll
            for (int r = 0; r < 4; r++) acc[m][n][r] = 0.f;

    issue(0, 0);

    for (int c = 0; c < N_CHUNKS; c++) {
        const int s = c & 1;
        if (c + 1 < N_CHUNKS) issue(c + 1, s ^ 1);
        if (c + 1 < N_CHUNKS) { CP_WAIT1(); } else { CP_WAIT0(); }
        __syncthreads();

        const uint32_t xsS = xs_u + (uint32_t)(s * XS_STG);
        const uint32_t csS = cs_u + (uint32_t)(s * CS_STG);

        #pragma unroll
        for (int ds = 0; ds < 2; ds++) {         // two k16 steps cover 32 d
            uint32_t af[4][4];
            #pragma unroll
            for (int m = 0; m < 4; m++)
                ldsm4(af[m], csS +
                    (uint32_t)(((kwb + m * 16 + lm_k) * CROWH + ds * 16 + lm_d8) * 2));
            #pragma unroll
            for (int n = 0; n < 4; n++) {
                uint32_t bf[2];
                ldsm2t(bf, xsS +
                    (uint32_t)(((ds * 16 + lm_k) * XROWH + twb + n * 8) * 2));
                #pragma unroll
                for (int m = 0; m < 4; m++) mma_f16(acc[m][n], af[m], bf);
            }
        }

        // ---- end of a k-pass: fold top-2 (rows=k, cols=t), merge, reset ----
        if ((c & 15) == 15) {
            const int k0p  = (c >> 4) << 7;
            const int slot = warp_k * 8 + gid;
            const int kb   = k0p + kwb;
            #pragma unroll
            for (int n = 0; n < 4; n++) {
                const int te = twb + n * 8 + 2 * tig;
                float v1e = 3.4e38f, v2e = 3.4e38f; int i1e = 0, i2e = 0;
                float v1o = 3.4e38f, v2o = 3.4e38f; int i1o = 0, i2o = 0;
                #pragma unroll
                for (int m = 0; m < 4; m++) {
                    const int kA = kb + m * 16 + gid;
                    const float cqA = __ldg(&g_csq[kA]);
                    const float cqB = __ldg(&g_csq[kA + 8]);
                    top2(cqA - 2.f * acc[m][n][0], kA,     v1e, i1e, v2e, i2e);
                    top2(cqB - 2.f * acc[m][n][2], kA + 8, v1e, i1e, v2e, i2e);
                    top2(cqA - 2.f * acc[m][n][1], kA,     v1o, i1o, v2o, i2o);
                    top2(cqB - 2.f * acc[m][n][3], kA + 8, v1o, i1o, v2o, i2o);
                }
                rv1[slot * 128 + te] = v1e;     ri1[slot * 128 + te] = i1e;
                rv2[slot * 128 + te] = v2e;     ri2[slot * 128 + te] = i2e;
                rv1[slot * 128 + te + 1] = v1o; ri1[slot * 128 + te + 1] = i1o;
                rv2[slot * 128 + te + 1] = v2o; ri2[slot * 128 + te + 1] = i2o;
            }
            #pragma unroll
            for (int m = 0; m < 4; m++)
                #pragma unroll
                for (int n = 0; n < 4; n++)
                    #pragma unroll
                    for (int r = 0; r < 4; r++) acc[m][n][r] = 0.f;
            __syncthreads();
            if (tid < TILE_T) {
                float v1 = bv1[tid], v2 = bv2[tid];
                int   i1 = bi1[tid], i2 = bi2[tid];
                #pragma unroll
                for (int r = 0; r < 16; r++) {
                    top2(rv1[r * 128 + tid], ri1[r * 128 + tid], v1, i1, v2, i2);
                    top2(rv2[r * 128 + tid], ri2[r * 128 + tid], v1, i1, v2, i2);
                }
                bv1[tid] = v1; bi1[tid] = i1; bv2[tid] = v2; bi2[tid] = i2;
            }
        }
        __syncthreads();
    }

    // ---- exact fp32 rescore of top-2 candidates (raw x, raw cb) ----
    float* XSf = (float*)smb;                    // reuse smem as f32 staging
    const int p    = tid >> 1;
    const int half = tid & 1;
    const int cand = half ? bi2[p] : bi1[p];
    const float* crow = cb + (size_t)cand * DD;
    float dot = 0.f;
    for (int dc = 0; dc < 16; dc++) {
        const int d0 = dc * 32;
        __syncthreads();
        #pragma unroll
        for (int l = 0; l < 4; l++) {
            int e  = l * 256 + tid;
            int d  = e >> 5;
            int t4 = e & 31;
            *(float4*)&XSf[d * XS_STRIDE + t4 * 4] =
                *(const float4*)(xb + (size_t)(d0 + d) * TT + t4 * 4);
        }
        __syncthreads();
        #pragma unroll
        for (int j = 0; j < 8; j++) {
            float4 cv = *(const float4*)(crow + d0 + 4 * j);
            dot = fmaf(XSf[(4 * j + 0) * XS_STRIDE + p], cv.x, dot);
            dot = fmaf(XSf[(4 * j + 1) * XS_STRIDE + p], cv.y, dot);
            dot = fmaf(XSf[(4 * j + 2) * XS_STRIDE + p], cv.z, dot);
            dot = fmaf(XSf[(4 * j + 3) * XS_STRIDE + p], cv.w, dot);
        }
    }
    rv1[tid] = __ldg(&g_csq[cand]) - 2.f * dot;
    __syncthreads();
    if (tid < TILE_T) {
        float sA = rv1[2 * tid], sB = rv1[2 * tid + 1];
        int   iA = bi1[tid],     iB = bi2[tid];
        int fin = (sB < sA || (sB == sA && iB < iA)) ? iB : iA;
        bi1[tid] = fin;
        iout[(size_t)b * TT + t0 + tid] = (float)fin;
    }
    __syncthreads();

    // ---- gather quantized: t-coalesced stores ----
    float* qb = qout + (size_t)b * DD * TT + t0;
    for (int e = tid; e < DD * TILE_T; e += 256) {
        int t = e & (TILE_T - 1);
        int d = e >> 7;
        qb[(size_t)d * TT + t] = cb[(size_t)bi1[t] * DD + d];
    }
}

extern "C" void kernel_launch(void* const* d_in, const int* in_sizes, int n_in,
                              void* d_out, int out_size) {
    const float* x  = (const float*)d_in[0];   // [B, D, T] fp32
    const float* cb = (const float*)d_in[1];   // [K, D]    fp32

    float* qout = (float*)d_out;                         // [B, D, T]
    float* iout = (float*)d_out + (size_t)BB * DD * TT;  // [B, T] as float

    cudaFuncSetAttribute(vq_kernel, cudaFuncAttributeMaxDynamicSharedMemorySize,
                         SMEM_BYTES);

    __half* xh;  cudaGetSymbolAddress((void**)&xh,  g_xh);
    __half* cbh; cudaGetSymbolAddress((void**)&cbh, g_cbh);

    csq_kernel<<<(KK * 32 + 255) / 256, 256>>>(cb);
    {
        int n8 = (BB * DD * TT) / 8;
        prep_half<<<(n8 + 255) / 256, 256>>>(x, xh, n8);
    }
    {
        int n8 = (KK * DD) / 8;
        prep_half<<<(n8 + 255) / 256, 256>>>(cb, cbh, n8);
    }
    vq_kernel<<<(BB * TT) / TILE_T, 256, SMEM_BYTES>>>(x, cb, qout, iout);
}